// round 1
// baseline (speedup 1.0000x reference)
#include <cuda_runtime.h>
#include <cstddef>

#define BATCH 4
#define CCH 256
#define NTOK 4096
#define GROUPS 32
#define CPG (CCH / GROUPS)   // 8 channels per group
#define EPSV 1e-6f

// Scratch (device globals; allocation is forbidden)
__device__ float g_xn[(size_t)BATCH * CCH * NTOK];              // 16 MB
__device__ float g_q [(size_t)BATCH * CCH * NTOK];              // 16 MB
__device__ float g_k [(size_t)BATCH * CCH * NTOK];              // 16 MB
__device__ float g_v [(size_t)BATCH * CCH * NTOK];              // 16 MB
__device__ float g_o [(size_t)BATCH * CCH * NTOK];              // 16 MB
__device__ float g_attn[(size_t)BATCH * NTOK * NTOK];           // 256 MB

// ---------------------------------------------------------------------------
// GroupNorm: one block per (batch, group); group = 8 channels x 4096 spatial
// ---------------------------------------------------------------------------
__global__ void groupnorm_kernel(const float* __restrict__ x,
                                 const float* __restrict__ w,
                                 const float* __restrict__ b) {
    int g  = blockIdx.x % GROUPS;
    int bb = blockIdx.x / GROUPS;
    const float* xp = x    + ((size_t)bb * CCH + g * CPG) * NTOK;
    float*       op = g_xn + ((size_t)bb * CCH + g * CPG) * NTOK;
    int tid = threadIdx.x;
    const int n = CPG * NTOK;  // 32768

    float s = 0.f, s2 = 0.f;
    for (int i = tid; i < n; i += blockDim.x) {
        float v = xp[i];
        s += v; s2 += v * v;
    }
    __shared__ float sh0[256], sh1[256];
    sh0[tid] = s; sh1[tid] = s2;
    __syncthreads();
    for (int off = 128; off > 0; off >>= 1) {
        if (tid < off) { sh0[tid] += sh0[tid + off]; sh1[tid] += sh1[tid + off]; }
        __syncthreads();
    }
    float mean = sh0[0] / (float)n;
    float var  = sh1[0] / (float)n - mean * mean;
    float rstd = rsqrtf(var + EPSV);

    for (int i = tid; i < n; i += blockDim.x) {
        int ch = g * CPG + i / NTOK;
        op[i] = (xp[i] - mean) * rstd * w[ch] + b[ch];
    }
}

// ---------------------------------------------------------------------------
// Generic tiled SGEMM: C[m][n] = alpha * sum_k A(m,k)*B(k,n) + bias[m] + resid
// 64x64 tile, BK=16, 256 threads, 4x4 per-thread microtile.
// TA: A(m,k) = A[k*lda + m]   (transposed storage)
// TB: B(k,n) = B[n*ldb + k]
// ---------------------------------------------------------------------------
template <bool TA, bool TB>
__global__ void sgemm_kernel(const float* __restrict__ A,
                             const float* __restrict__ B,
                             const float* __restrict__ bias,
                             const float* __restrict__ resid,
                             float* __restrict__ Cmat,
                             int M, int N, int K,
                             int lda, int ldb, int ldc,
                             size_t strideA, size_t strideB,
                             size_t strideC, size_t strideR,
                             float alpha) {
    int bz = blockIdx.z;
    A    += (size_t)bz * strideA;
    B    += (size_t)bz * strideB;
    Cmat += (size_t)bz * strideC;
    if (resid) resid += (size_t)bz * strideR;

    __shared__ float As[16][64 + 1];  // [k][m]
    __shared__ float Bs[16][64 + 1];  // [k][n]

    int tid = threadIdx.x;
    int m0 = blockIdx.y * 64;
    int n0 = blockIdx.x * 64;
    int tm = (tid / 16) * 4;
    int tn = (tid % 16) * 4;

    float acc[4][4] = {};

    for (int k0 = 0; k0 < K; k0 += 16) {
        // Load A tile (64 m x 16 k) -> As[k][m]
        if (TA) {
            // A[k*lda + m]: make m contiguous per warp
            for (int i = tid; i < 64 * 16; i += 256) {
                int kk = i / 64, mm = i % 64;
                As[kk][mm] = A[(size_t)(k0 + kk) * lda + (m0 + mm)];
            }
        } else {
            for (int i = tid; i < 64 * 16; i += 256) {
                int mm = i / 16, kk = i % 16;
                As[kk][mm] = A[(size_t)(m0 + mm) * lda + (k0 + kk)];
            }
        }
        // Load B tile (16 k x 64 n) -> Bs[k][n]
        if (TB) {
            for (int i = tid; i < 64 * 16; i += 256) {
                int nn = i / 16, kk = i % 16;
                Bs[kk][nn] = B[(size_t)(n0 + nn) * ldb + (k0 + kk)];
            }
        } else {
            for (int i = tid; i < 64 * 16; i += 256) {
                int kk = i / 64, nn = i % 64;
                Bs[kk][nn] = B[(size_t)(k0 + kk) * ldb + (n0 + nn)];
            }
        }
        __syncthreads();

        #pragma unroll
        for (int kk = 0; kk < 16; kk++) {
            float a[4], bv[4];
            #pragma unroll
            for (int i = 0; i < 4; i++) a[i] = As[kk][tm + i];
            #pragma unroll
            for (int j = 0; j < 4; j++) bv[j] = Bs[kk][tn + j];
            #pragma unroll
            for (int i = 0; i < 4; i++)
                #pragma unroll
                for (int j = 0; j < 4; j++)
                    acc[i][j] += a[i] * bv[j];
        }
        __syncthreads();
    }

    #pragma unroll
    for (int i = 0; i < 4; i++) {
        int m = m0 + tm + i;
        float bm = bias ? bias[m] : 0.f;
        #pragma unroll
        for (int j = 0; j < 4; j++) {
            int n = n0 + tn + j;
            float vv = acc[i][j] * alpha + bm;
            if (resid) vv += resid[(size_t)m * ldc + n];
            Cmat[(size_t)m * ldc + n] = vv;
        }
    }
}

// ---------------------------------------------------------------------------
// Row softmax over g_attn: grid (NTOK rows, BATCH)
// ---------------------------------------------------------------------------
__global__ void softmax_kernel() {
    size_t row = (size_t)blockIdx.y * NTOK + blockIdx.x;
    float* p = g_attn + row * NTOK;
    int tid = threadIdx.x;
    __shared__ float sh[256];

    float mx = -1e30f;
    for (int i = tid; i < NTOK; i += 256) mx = fmaxf(mx, p[i]);
    sh[tid] = mx; __syncthreads();
    for (int off = 128; off > 0; off >>= 1) {
        if (tid < off) sh[tid] = fmaxf(sh[tid], sh[tid + off]);
        __syncthreads();
    }
    mx = sh[0];
    __syncthreads();

    float s = 0.f;
    for (int i = tid; i < NTOK; i += 256) {
        float e = __expf(p[i] - mx);
        p[i] = e;
        s += e;
    }
    sh[tid] = s; __syncthreads();
    for (int off = 128; off > 0; off >>= 1) {
        if (tid < off) sh[tid] += sh[tid + off];
        __syncthreads();
    }
    float inv = 1.f / sh[0];
    for (int i = tid; i < NTOK; i += 256) p[i] *= inv;
}

// ---------------------------------------------------------------------------
extern "C" void kernel_launch(void* const* d_in, const int* in_sizes, int n_in,
                              void* d_out, int out_size) {
    const float* x    = (const float*)d_in[0];
    const float* gn_w = (const float*)d_in[1];
    const float* gn_b = (const float*)d_in[2];
    const float* wq   = (const float*)d_in[3];
    const float* bq   = (const float*)d_in[4];
    const float* wk   = (const float*)d_in[5];
    const float* bk   = (const float*)d_in[6];
    const float* wv   = (const float*)d_in[7];
    const float* bv   = (const float*)d_in[8];
    const float* wo   = (const float*)d_in[9];
    const float* bo   = (const float*)d_in[10];
    float* out = (float*)d_out;

    float *p_xn, *p_q, *p_k, *p_v, *p_o, *p_attn;
    cudaGetSymbolAddress((void**)&p_xn,   g_xn);
    cudaGetSymbolAddress((void**)&p_q,    g_q);
    cudaGetSymbolAddress((void**)&p_k,    g_k);
    cudaGetSymbolAddress((void**)&p_v,    g_v);
    cudaGetSymbolAddress((void**)&p_o,    g_o);
    cudaGetSymbolAddress((void**)&p_attn, g_attn);

    const size_t SB = (size_t)CCH * NTOK;          // per-batch feature-map stride
    const size_t SA = (size_t)NTOK * NTOK;         // per-batch attn stride
    const float scale = 0.0625f;                   // 256^-0.5

    dim3 blk(256);

    // 1) GroupNorm
    groupnorm_kernel<<<BATCH * GROUPS, blk>>>(x, gn_w, gn_b);

    // 2) Q, K, V projections: [256x256] @ [256x4096] per batch
    dim3 gproj(NTOK / 64, CCH / 64, BATCH);
    sgemm_kernel<false, false><<<gproj, blk>>>(wq, p_xn, bq, nullptr, p_q,
        CCH, NTOK, CCH, CCH, NTOK, NTOK, 0, SB, SB, 0, 1.0f);
    sgemm_kernel<false, false><<<gproj, blk>>>(wk, p_xn, bk, nullptr, p_k,
        CCH, NTOK, CCH, CCH, NTOK, NTOK, 0, SB, SB, 0, 1.0f);
    sgemm_kernel<false, false><<<gproj, blk>>>(wv, p_xn, bv, nullptr, p_v,
        CCH, NTOK, CCH, CCH, NTOK, NTOK, 0, SB, SB, 0, 1.0f);

    // 3) Scores: S[i][j] = scale * sum_c q[c][i] * k[c][j]   (A transposed)
    dim3 gscore(NTOK / 64, NTOK / 64, BATCH);
    sgemm_kernel<true, false><<<gscore, blk>>>(p_q, p_k, nullptr, nullptr, p_attn,
        NTOK, NTOK, CCH, NTOK, NTOK, NTOK, SB, SB, SA, 0, scale);

    // 4) Row softmax
    dim3 gsm(NTOK, BATCH);
    softmax_kernel<<<gsm, blk>>>();

    // 5) out[c][i] = sum_j v[c][j] * P[i][j]   (B transposed)
    dim3 gpv(NTOK / 64, CCH / 64, BATCH);
    sgemm_kernel<false, true><<<gpv, blk>>>(p_v, p_attn, nullptr, nullptr, p_o,
        CCH, NTOK, NTOK, NTOK, NTOK, NTOK, SB, SA, SB, 0, 1.0f);

    // 6) Output projection + bias + residual
    sgemm_kernel<false, false><<<gproj, blk>>>(wo, p_o, bo, x, out,
        CCH, NTOK, CCH, CCH, NTOK, NTOK, 0, SB, SB, SB, 1.0f);
}

// round 3
// speedup vs baseline: 4.8023x; 4.8023x over previous
#include <cuda_runtime.h>
#include <cstdint>
#include <cstddef>

#define BATCH 4
#define CCH 256
#define NTOK 4096
#define GROUPS 32
#define CPG (CCH / GROUPS)
#define EPSV 1e-6f

// ---------------- scratch (no allocation allowed) ----------------
__device__ float g_xn[(size_t)BATCH * CCH * NTOK];
__device__ float g_q [(size_t)BATCH * CCH * NTOK];
__device__ float g_k [(size_t)BATCH * CCH * NTOK];
__device__ float g_v [(size_t)BATCH * CCH * NTOK];
__device__ float g_o [(size_t)BATCH * CCH * NTOK];
__device__ float g_attn[(size_t)BATCH * NTOK * NTOK];

// ---------------- helpers ----------------
__device__ __forceinline__ uint32_t f2tf(float f) {
    uint32_t u;
    asm("cvt.rna.tf32.f32 %0, %1;" : "=r"(u) : "f"(f));
    return u;
}

__device__ __forceinline__ void mma8(float* c, const uint32_t* a,
                                     uint32_t b0, uint32_t b1) {
    asm volatile(
        "mma.sync.aligned.m16n8k8.row.col.f32.tf32.tf32.f32 "
        "{%0,%1,%2,%3}, {%4,%5,%6,%7}, {%8,%9}, {%0,%1,%2,%3};"
        : "+f"(c[0]), "+f"(c[1]), "+f"(c[2]), "+f"(c[3])
        : "r"(a[0]), "r"(a[1]), "r"(a[2]), "r"(a[3]), "r"(b0), "r"(b1));
}

// ---------------------------------------------------------------------------
// GroupNorm
// ---------------------------------------------------------------------------
__global__ void groupnorm_kernel(const float* __restrict__ x,
                                 const float* __restrict__ w,
                                 const float* __restrict__ b) {
    int g  = blockIdx.x % GROUPS;
    int bb = blockIdx.x / GROUPS;
    const float* xp = x    + ((size_t)bb * CCH + g * CPG) * NTOK;
    float*       op = g_xn + ((size_t)bb * CCH + g * CPG) * NTOK;
    int tid = threadIdx.x;
    const int n = CPG * NTOK;

    float s = 0.f, s2 = 0.f;
    for (int i = tid; i < n; i += blockDim.x) {
        float v = xp[i];
        s += v; s2 += v * v;
    }
    __shared__ float sh0[256], sh1[256];
    sh0[tid] = s; sh1[tid] = s2;
    __syncthreads();
    for (int off = 128; off > 0; off >>= 1) {
        if (tid < off) { sh0[tid] += sh0[tid + off]; sh1[tid] += sh1[tid + off]; }
        __syncthreads();
    }
    float mean = sh0[0] / (float)n;
    float var  = sh1[0] / (float)n - mean * mean;
    float rstd = rsqrtf(var + EPSV);

    for (int i = tid; i < n; i += blockDim.x) {
        int ch = g * CPG + i / NTOK;
        op[i] = (xp[i] - mean) * rstd * w[ch] + b[ch];
    }
}

// ---------------------------------------------------------------------------
// Row softmax: whole 4096-row in registers (16 floats/thread, 256 threads)
// ---------------------------------------------------------------------------
__global__ void softmax_kernel() {
    size_t row = (size_t)blockIdx.y * NTOK + blockIdx.x;
    float* p = g_attn + row * NTOK;
    int tid = threadIdx.x;
    __shared__ float sh[256];

    float4 vv[4];
    #pragma unroll
    for (int i = 0; i < 4; i++)
        vv[i] = ((const float4*)p)[tid + i * 256];

    float mx = -1e30f;
    #pragma unroll
    for (int i = 0; i < 4; i++)
        mx = fmaxf(mx, fmaxf(fmaxf(vv[i].x, vv[i].y), fmaxf(vv[i].z, vv[i].w)));
    sh[tid] = mx; __syncthreads();
    for (int off = 128; off > 0; off >>= 1) {
        if (tid < off) sh[tid] = fmaxf(sh[tid], sh[tid + off]);
        __syncthreads();
    }
    mx = sh[0];
    __syncthreads();

    float s = 0.f;
    #pragma unroll
    for (int i = 0; i < 4; i++) {
        vv[i].x = __expf(vv[i].x - mx); vv[i].y = __expf(vv[i].y - mx);
        vv[i].z = __expf(vv[i].z - mx); vv[i].w = __expf(vv[i].w - mx);
        s += vv[i].x + vv[i].y + vv[i].z + vv[i].w;
    }
    sh[tid] = s; __syncthreads();
    for (int off = 128; off > 0; off >>= 1) {
        if (tid < off) sh[tid] += sh[tid + off];
        __syncthreads();
    }
    float inv = 1.f / sh[0];
    #pragma unroll
    for (int i = 0; i < 4; i++) {
        vv[i].x *= inv; vv[i].y *= inv; vv[i].z *= inv; vv[i].w *= inv;
        ((float4*)p)[tid + i * 256] = vv[i];
    }
}

// ---------------------------------------------------------------------------
// TF32 mma.sync GEMM: C[M,N] = alpha*A·B + bias[m] + resid
// Block tile 128x128, BK=32, 256 threads = 8 warps, warp tile 32x64.
// AMODE 0: A(m,k)=A[m*lda+k]  (k contiguous)
// AMODE 1: A(m,k)=A[k*lda+m]  (m contiguous)
// BMODE 0: B(k,n)=B[n*ldb+k]  (k contiguous)
// BMODE 1: B(k,n)=B[k*ldb+n]  (n contiguous)
// SMEM: AMODE0 -> As[m][k] stride 36; AMODE1 -> As[k][m] stride 136
//       BMODE0 -> Bs[n][k] stride 36; BMODE1 -> Bs[k][n] stride 136
// ---------------------------------------------------------------------------
template <int AMODE, int BMODE>
__global__ void __launch_bounds__(256)
mma_gemm(const float* __restrict__ A, const float* __restrict__ B,
         const float* __restrict__ bias, const float* __restrict__ resid,
         float* __restrict__ C,
         int K, int lda, int ldb, int ldc,
         size_t sA, size_t sB, size_t sC, size_t sR, float alpha) {
    __shared__ float As[4608];   // max(128*36, 32*136)
    __shared__ float Bs[4608];

    const int bz = blockIdx.z;
    A += (size_t)bz * sA;
    B += (size_t)bz * sB;
    C += (size_t)bz * sC;
    if (resid) resid += (size_t)bz * sR;

    const int M0 = blockIdx.y * 128;
    const int N0 = blockIdx.x * 128;
    const int tid  = threadIdx.x;
    const int lane = tid & 31;
    const int wid  = tid >> 5;
    const int wm = wid >> 1;       // 0..3 -> 32 rows each
    const int wn = wid & 1;        // 0..1 -> 64 cols each
    const int g   = lane >> 2;     // 0..7
    const int tig = lane & 3;      // 0..3

    float acc[2][8][4];
    #pragma unroll
    for (int i = 0; i < 2; i++)
        #pragma unroll
        for (int j = 0; j < 8; j++)
            #pragma unroll
            for (int q = 0; q < 4; q++) acc[i][j][q] = 0.f;

    const int KT = K / 32;
    for (int kt = 0; kt < KT; kt++) {
        const int k0 = kt * 32;
        __syncthreads();

        // ---- stage A (4096 floats, tf32-converted) ----
        #pragma unroll
        for (int t = 0; t < 4; t++) {
            int idx = tid + t * 256;
            if (AMODE == 0) {
                int row = idx >> 3, c4 = (idx & 7) * 4;
                float4 v = *(const float4*)(A + (size_t)(M0 + row) * lda + k0 + c4);
                float* dst = As + row * 36 + c4;
                dst[0] = __uint_as_float(f2tf(v.x));
                dst[1] = __uint_as_float(f2tf(v.y));
                dst[2] = __uint_as_float(f2tf(v.z));
                dst[3] = __uint_as_float(f2tf(v.w));
            } else {
                int kk = idx >> 5, m4 = (idx & 31) * 4;
                float4 v = *(const float4*)(A + (size_t)(k0 + kk) * lda + M0 + m4);
                float* dst = As + kk * 136 + m4;
                dst[0] = __uint_as_float(f2tf(v.x));
                dst[1] = __uint_as_float(f2tf(v.y));
                dst[2] = __uint_as_float(f2tf(v.z));
                dst[3] = __uint_as_float(f2tf(v.w));
            }
        }
        // ---- stage B ----
        #pragma unroll
        for (int t = 0; t < 4; t++) {
            int idx = tid + t * 256;
            if (BMODE == 0) {
                int row = idx >> 3, c4 = (idx & 7) * 4;   // row = n
                float4 v = *(const float4*)(B + (size_t)(N0 + row) * ldb + k0 + c4);
                float* dst = Bs + row * 36 + c4;
                dst[0] = __uint_as_float(f2tf(v.x));
                dst[1] = __uint_as_float(f2tf(v.y));
                dst[2] = __uint_as_float(f2tf(v.z));
                dst[3] = __uint_as_float(f2tf(v.w));
            } else {
                int kk = idx >> 5, n4 = (idx & 31) * 4;
                float4 v = *(const float4*)(B + (size_t)(k0 + kk) * ldb + N0 + n4);
                float* dst = Bs + kk * 136 + n4;
                dst[0] = __uint_as_float(f2tf(v.x));
                dst[1] = __uint_as_float(f2tf(v.y));
                dst[2] = __uint_as_float(f2tf(v.z));
                dst[3] = __uint_as_float(f2tf(v.w));
            }
        }
        __syncthreads();

        // ---- compute: 4 k-steps of k=8 ----
        #pragma unroll
        for (int ks = 0; ks < 4; ks++) {
            uint32_t a[2][4];
            #pragma unroll
            for (int i = 0; i < 2; i++) {
                int m0f = wm * 32 + i * 16;
                if (AMODE == 0) {
                    const float* p = As + (m0f + g) * 36 + ks * 8 + tig;
                    a[i][0] = __float_as_uint(p[0]);
                    a[i][1] = __float_as_uint(p[8 * 36]);
                    a[i][2] = __float_as_uint(p[4]);
                    a[i][3] = __float_as_uint(p[8 * 36 + 4]);
                } else {
                    const float* p = As + (ks * 8 + tig) * 136 + m0f + g;
                    a[i][0] = __float_as_uint(p[0]);
                    a[i][1] = __float_as_uint(p[8]);
                    a[i][2] = __float_as_uint(p[4 * 136]);
                    a[i][3] = __float_as_uint(p[4 * 136 + 8]);
                }
            }
            #pragma unroll
            for (int j = 0; j < 8; j++) {
                int n0f = wn * 64 + j * 8;
                uint32_t b0, b1;
                if (BMODE == 0) {
                    const float* p = Bs + (n0f + g) * 36 + ks * 8 + tig;
                    b0 = __float_as_uint(p[0]);
                    b1 = __float_as_uint(p[4]);
                } else {
                    const float* p = Bs + (ks * 8 + tig) * 136 + n0f + g;
                    b0 = __float_as_uint(p[0]);
                    b1 = __float_as_uint(p[4 * 136]);
                }
                mma8(acc[0][j], a[0], b0, b1);
                mma8(acc[1][j], a[1], b0, b1);
            }
        }
    }

    // ---- epilogue ----
    #pragma unroll
    for (int i = 0; i < 2; i++) {
        int m = M0 + wm * 32 + i * 16 + g;
        float bm0 = bias ? bias[m]     : 0.f;
        float bm1 = bias ? bias[m + 8] : 0.f;
        #pragma unroll
        for (int j = 0; j < 8; j++) {
            int n = N0 + wn * 64 + j * 8 + tig * 2;
            float2 v0, v1;
            v0.x = acc[i][j][0] * alpha + bm0;
            v0.y = acc[i][j][1] * alpha + bm0;
            v1.x = acc[i][j][2] * alpha + bm1;
            v1.y = acc[i][j][3] * alpha + bm1;
            if (resid) {
                float2 r0 = *(const float2*)(resid + (size_t)m * ldc + n);
                float2 r1 = *(const float2*)(resid + (size_t)(m + 8) * ldc + n);
                v0.x += r0.x; v0.y += r0.y; v1.x += r1.x; v1.y += r1.y;
            }
            *(float2*)(C + (size_t)m * ldc + n)       = v0;
            *(float2*)(C + (size_t)(m + 8) * ldc + n) = v1;
        }
    }
}

// ---------------------------------------------------------------------------
extern "C" void kernel_launch(void* const* d_in, const int* in_sizes, int n_in,
                              void* d_out, int out_size) {
    const float* x    = (const float*)d_in[0];
    const float* gn_w = (const float*)d_in[1];
    const float* gn_b = (const float*)d_in[2];
    const float* wq   = (const float*)d_in[3];
    const float* bq   = (const float*)d_in[4];
    const float* wk   = (const float*)d_in[5];
    const float* bk   = (const float*)d_in[6];
    const float* wv   = (const float*)d_in[7];
    const float* bv   = (const float*)d_in[8];
    const float* wo   = (const float*)d_in[9];
    const float* bo   = (const float*)d_in[10];
    float* out = (float*)d_out;

    float *p_xn, *p_q, *p_k, *p_v, *p_o, *p_attn;
    cudaGetSymbolAddress((void**)&p_xn,   g_xn);
    cudaGetSymbolAddress((void**)&p_q,    g_q);
    cudaGetSymbolAddress((void**)&p_k,    g_k);
    cudaGetSymbolAddress((void**)&p_v,    g_v);
    cudaGetSymbolAddress((void**)&p_o,    g_o);
    cudaGetSymbolAddress((void**)&p_attn, g_attn);

    const size_t SB = (size_t)CCH * NTOK;
    const size_t SA = (size_t)NTOK * NTOK;
    const float scale = 0.0625f;   // 256^-0.5

    // 1) GroupNorm
    groupnorm_kernel<<<BATCH * GROUPS, 256>>>(x, gn_w, gn_b);

    // 2) Q/K/V projections: C[m,n] = W[m,k]*xn[k,n]  (A k-cont, B n-cont)
    dim3 gproj(NTOK / 128, CCH / 128, BATCH);
    mma_gemm<0, 1><<<gproj, 256>>>(wq, p_xn, bq, nullptr, p_q,
        CCH, CCH, NTOK, NTOK, 0, SB, SB, 0, 1.0f);
    mma_gemm<0, 1><<<gproj, 256>>>(wk, p_xn, bk, nullptr, p_k,
        CCH, CCH, NTOK, NTOK, 0, SB, SB, 0, 1.0f);
    mma_gemm<0, 1><<<gproj, 256>>>(wv, p_xn, bv, nullptr, p_v,
        CCH, CCH, NTOK, NTOK, 0, SB, SB, 0, 1.0f);

    // 3) Scores: S[i,j] = scale * sum_c q[c,i]k[c,j]  (A m-cont, B n-cont)
    dim3 gscore(NTOK / 128, NTOK / 128, BATCH);
    mma_gemm<1, 1><<<gscore, 256>>>(p_q, p_k, nullptr, nullptr, p_attn,
        CCH, NTOK, NTOK, NTOK, SB, SB, SA, 0, scale);

    // 4) Row softmax
    dim3 gsm(NTOK, BATCH);
    softmax_kernel<<<gsm, 256>>>();

    // 5) O[c,i] = sum_j v[c,j]P[i,j]  (A k-cont, B k-cont)
    dim3 gpv(NTOK / 128, CCH / 128, BATCH);
    mma_gemm<0, 0><<<gpv, 256>>>(p_v, p_attn, nullptr, nullptr, p_o,
        NTOK, NTOK, NTOK, NTOK, SB, SA, SB, 0, 1.0f);

    // 6) Output projection + bias + residual
    mma_gemm<0, 1><<<gproj, 256>>>(wo, p_o, bo, x, out,
        CCH, CCH, NTOK, NTOK, 0, SB, SB, SB, 1.0f);
}

// round 4
// speedup vs baseline: 11.1684x; 2.3256x over previous
#include <cuda_runtime.h>
#include <cuda_bf16.h>
#include <cstdint>
#include <cstddef>

#define BATCH 4
#define CCH 256
#define NTOK 4096
#define GROUPS 32
#define CPG 8
#define EPSV 1e-6f

typedef __nv_bfloat16 bf16;

// ---------------- scratch (device globals; 16B aligned via uint4) ----------
__device__ uint4 g_xnb4 [(size_t)BATCH * CCH * NTOK / 8];
__device__ uint4 g_qb4  [(size_t)BATCH * CCH * NTOK / 8];
__device__ uint4 g_kb4  [(size_t)BATCH * CCH * NTOK / 8];
__device__ uint4 g_vb4  [(size_t)BATCH * CCH * NTOK / 8];
__device__ uint4 g_ob4  [(size_t)BATCH * CCH * NTOK / 8];
__device__ uint4 g_attnb4[(size_t)BATCH * NTOK * NTOK / 8];
__device__ uint4 g_wb4[4][CCH * CCH / 8];

// ---------------- asm helpers ----------------
__device__ __forceinline__ uint32_t smem_u32(const void* p) {
    uint32_t a;
    asm("{ .reg .u64 t; cvta.to.shared.u64 t, %1; cvt.u32.u64 %0, t; }"
        : "=r"(a) : "l"(p));
    return a;
}
__device__ __forceinline__ void ldsm4(uint32_t* r, uint32_t a) {
    asm volatile("ldmatrix.sync.aligned.m8n8.x4.shared.b16 {%0,%1,%2,%3}, [%4];"
        : "=r"(r[0]), "=r"(r[1]), "=r"(r[2]), "=r"(r[3]) : "r"(a));
}
__device__ __forceinline__ void ldsm4t(uint32_t* r, uint32_t a) {
    asm volatile("ldmatrix.sync.aligned.m8n8.x4.trans.shared.b16 {%0,%1,%2,%3}, [%4];"
        : "=r"(r[0]), "=r"(r[1]), "=r"(r[2]), "=r"(r[3]) : "r"(a));
}
__device__ __forceinline__ void mma16(float* c, const uint32_t* a,
                                      uint32_t b0, uint32_t b1) {
    asm volatile(
        "mma.sync.aligned.m16n8k16.row.col.f32.bf16.bf16.f32 "
        "{%0,%1,%2,%3}, {%4,%5,%6,%7}, {%8,%9}, {%0,%1,%2,%3};"
        : "+f"(c[0]), "+f"(c[1]), "+f"(c[2]), "+f"(c[3])
        : "r"(a[0]), "r"(a[1]), "r"(a[2]), "r"(a[3]), "r"(b0), "r"(b1));
}
__device__ __forceinline__ void cp16(uint32_t d, const void* s) {
    asm volatile("cp.async.cg.shared.global [%0], [%1], 16;" :: "r"(d), "l"(s));
}

// ---------------------------------------------------------------------------
// Weight fp32 -> bf16 conversion (once per call, 65536 elems per matrix)
// ---------------------------------------------------------------------------
__global__ void convw_kernel(const float* wq, const float* wk,
                             const float* wv, const float* wo,
                             bf16* o0, bf16* o1, bf16* o2, bf16* o3) {
    int i = blockIdx.x * 256 + threadIdx.x;
    o0[i] = __float2bfloat16(wq[i]);
    o1[i] = __float2bfloat16(wk[i]);
    o2[i] = __float2bfloat16(wv[i]);
    o3[i] = __float2bfloat16(wo[i]);
}

// ---------------------------------------------------------------------------
// GroupNorm: fp32 in, bf16 out. One block per (batch, group).
// ---------------------------------------------------------------------------
__global__ void groupnorm_kernel(const float* __restrict__ x,
                                 const float* __restrict__ w,
                                 const float* __restrict__ b,
                                 bf16* __restrict__ xnb) {
    int g  = blockIdx.x % GROUPS;
    int bb = blockIdx.x / GROUPS;
    const float4* xp = (const float4*)(x + ((size_t)bb * CCH + g * CPG) * NTOK);
    bf16* op = xnb + ((size_t)bb * CCH + g * CPG) * NTOK;
    int tid = threadIdx.x;
    const int n4 = CPG * NTOK / 4;   // 8192

    float s = 0.f, s2 = 0.f;
    for (int i = tid; i < n4; i += 256) {
        float4 v = xp[i];
        s  += v.x + v.y + v.z + v.w;
        s2 += v.x*v.x + v.y*v.y + v.z*v.z + v.w*v.w;
    }
    __shared__ float sh0[256], sh1[256];
    sh0[tid] = s; sh1[tid] = s2;
    __syncthreads();
    for (int off = 128; off > 0; off >>= 1) {
        if (tid < off) { sh0[tid] += sh0[tid + off]; sh1[tid] += sh1[tid + off]; }
        __syncthreads();
    }
    const float nall = (float)(CPG * NTOK);
    float mean = sh0[0] / nall;
    float var  = sh1[0] / nall - mean * mean;
    float rstd = rsqrtf(var + EPSV);

    for (int i = tid; i < n4; i += 256) {
        int ch = g * CPG + (i * 4) / NTOK;
        float sc = rstd * w[ch];
        float sb = b[ch] - mean * sc;
        float4 v = xp[i];
        __nv_bfloat162 h0 = __floats2bfloat162_rn(v.x * sc + sb, v.y * sc + sb);
        __nv_bfloat162 h1 = __floats2bfloat162_rn(v.z * sc + sb, v.w * sc + sb);
        uint2 u;
        u.x = *(uint32_t*)&h0; u.y = *(uint32_t*)&h1;
        *(uint2*)(op + i * 4) = u;
    }
}

// ---------------------------------------------------------------------------
// Row softmax on bf16 attn: 4096 elems/row, 256 threads, 16 elems/thread regs
// ---------------------------------------------------------------------------
__global__ void softmax_kernel(bf16* __restrict__ attnb) {
    size_t row = (size_t)blockIdx.y * NTOK + blockIdx.x;
    uint4* p = (uint4*)(attnb + row * NTOK);   // 512 uint4
    int tid = threadIdx.x;
    __shared__ float sh[256];

    uint4 u[2];
    float f[16];
    #pragma unroll
    for (int i = 0; i < 2; i++) u[i] = p[tid + i * 256];
    #pragma unroll
    for (int i = 0; i < 2; i++) {
        __nv_bfloat162* h = (__nv_bfloat162*)&u[i];
        #pragma unroll
        for (int j = 0; j < 4; j++) {
            float2 v = __bfloat1622float2(h[j]);
            f[i*8 + 2*j] = v.x; f[i*8 + 2*j + 1] = v.y;
        }
    }

    float mx = -1e30f;
    #pragma unroll
    for (int i = 0; i < 16; i++) mx = fmaxf(mx, f[i]);
    sh[tid] = mx; __syncthreads();
    for (int off = 128; off > 0; off >>= 1) {
        if (tid < off) sh[tid] = fmaxf(sh[tid], sh[tid + off]);
        __syncthreads();
    }
    mx = sh[0];
    __syncthreads();

    float s = 0.f;
    #pragma unroll
    for (int i = 0; i < 16; i++) { f[i] = __expf(f[i] - mx); s += f[i]; }
    sh[tid] = s; __syncthreads();
    for (int off = 128; off > 0; off >>= 1) {
        if (tid < off) sh[tid] += sh[tid + off];
        __syncthreads();
    }
    float inv = 1.f / sh[0];

    #pragma unroll
    for (int i = 0; i < 2; i++) {
        __nv_bfloat162* h = (__nv_bfloat162*)&u[i];
        #pragma unroll
        for (int j = 0; j < 4; j++)
            h[j] = __floats2bfloat162_rn(f[i*8 + 2*j] * inv, f[i*8 + 2*j + 1] * inv);
        p[tid + i * 256] = u[i];
    }
}

// ---------------------------------------------------------------------------
// bf16 GEMM: C[M,N] = alpha*A·B (+ bias[m]) (+ resid), fp32 accumulate.
// Tile 128x128, BK=64, 256 threads = 8 warps (warp tile 32x64).
// cp.async double-buffered SMEM, ldmatrix fragments, mma.m16n8k16.
// AST 0: A global [m][k'] (k cont) -> smem [m][k] stride 72, ldmatrix
// AST 1: A global [k'][m] (m cont) -> smem [k][m] stride 136, ldmatrix.trans
// BST 0: B global [n][k'] (k cont) -> smem [n][k] stride 72, ldmatrix
// BST 1: B global [k'][n] (n cont) -> smem [k][n] stride 136, ldmatrix.trans
// OUTF 0: bf16 out (+bias).  OUTF 1: fp32 out + bias + resid.
// ---------------------------------------------------------------------------
#define ABYTES 18432u
#define BUFBYTES 36864u
#define SMEM_DYN (2 * 36864)

template <int AST, int BST, int OUTF>
__global__ void __launch_bounds__(256, 2)
bgemm(const bf16* __restrict__ A, const bf16* __restrict__ B,
      const float* __restrict__ bias, const float* __restrict__ resid,
      void* __restrict__ Cv, int K, int lda, int ldb, int ldc,
      size_t sA, size_t sB, size_t sC, size_t sR, float alpha) {
    extern __shared__ __align__(16) char smem[];
    const int bz = blockIdx.z;
    A += (size_t)bz * sA;
    B += (size_t)bz * sB;

    const int M0 = blockIdx.y * 128;
    const int N0 = blockIdx.x * 128;
    const int tid  = threadIdx.x;
    const int lane = tid & 31;
    const int wid  = tid >> 5;
    const int wm = wid >> 1;      // 0..3
    const int wn = wid & 1;       // 0..1
    const int g  = lane >> 2;
    const int t  = lane & 3;
    const int l7  = lane & 7;
    const int l15 = lane & 15;
    const int b3 = (lane >> 3) & 1;
    const int b4 = (lane >> 4) & 1;

    const uint32_t smem_u = smem_u32(smem);

    float acc[2][8][4];
    #pragma unroll
    for (int i = 0; i < 2; i++)
        #pragma unroll
        for (int j = 0; j < 8; j++)
            #pragma unroll
            for (int q = 0; q < 4; q++) acc[i][j][q] = 0.f;

    const int KT = K >> 6;

    // -------- stage tile kt into buffer buf (pure cp.async 16B) --------
    auto stage = [&](int kt, int buf) {
        uint32_t ab = smem_u + (uint32_t)buf * BUFBYTES;
        uint32_t bbs = ab + ABYTES;
        int k0 = kt << 6;
        #pragma unroll
        for (int i = 0; i < 4; i++) {
            int c = tid + i * 256;
            if (AST == 0) {
                int m = c >> 3, kc = c & 7;
                cp16(ab + (uint32_t)(m * 72 + kc * 8) * 2,
                     A + (size_t)(M0 + m) * lda + k0 + kc * 8);
            } else {
                int k = c >> 4, mc = c & 15;
                cp16(ab + (uint32_t)(k * 136 + mc * 8) * 2,
                     A + (size_t)(k0 + k) * lda + M0 + mc * 8);
            }
        }
        #pragma unroll
        for (int i = 0; i < 4; i++) {
            int c = tid + i * 256;
            if (BST == 0) {
                int n = c >> 3, kc = c & 7;
                cp16(bbs + (uint32_t)(n * 72 + kc * 8) * 2,
                     B + (size_t)(N0 + n) * ldb + k0 + kc * 8);
            } else {
                int k = c >> 4, nc = c & 15;
                cp16(bbs + (uint32_t)(k * 136 + nc * 8) * 2,
                     B + (size_t)(k0 + k) * ldb + N0 + nc * 8);
            }
        }
    };

    stage(0, 0);
    asm volatile("cp.async.commit_group;" ::: "memory");

    for (int kt = 0; kt < KT; kt++) {
        if (kt + 1 < KT) {
            stage(kt + 1, (kt + 1) & 1);
            asm volatile("cp.async.commit_group;" ::: "memory");
            asm volatile("cp.async.wait_group 1;" ::: "memory");
        } else {
            asm volatile("cp.async.wait_group 0;" ::: "memory");
        }
        __syncthreads();

        uint32_t ab = smem_u + (uint32_t)(kt & 1) * BUFBYTES;
        uint32_t bbs = ab + ABYTES;

        #pragma unroll
        for (int ks = 0; ks < 4; ks++) {
            uint32_t af[2][4];
            #pragma unroll
            for (int i = 0; i < 2; i++) {
                if (AST == 0) {
                    uint32_t addr = ab + 2u * (uint32_t)(
                        (wm * 32 + i * 16 + l15) * 72 + ks * 16 + b4 * 8);
                    ldsm4(af[i], addr);
                } else {
                    uint32_t addr = ab + 2u * (uint32_t)(
                        (ks * 16 + b4 * 8 + l7) * 136 + wm * 32 + i * 16 + b3 * 8);
                    ldsm4t(af[i], addr);
                }
            }
            uint32_t bfr[4][4];   // per j2: {b0a, b1a, b0b, b1b}
            #pragma unroll
            for (int j2 = 0; j2 < 4; j2++) {
                int nb = wn * 64 + j2 * 16;
                if (BST == 0) {
                    uint32_t addr = bbs + 2u * (uint32_t)(
                        (nb + b4 * 8 + l7) * 72 + ks * 16 + b3 * 8);
                    ldsm4(bfr[j2], addr);
                } else {
                    uint32_t addr = bbs + 2u * (uint32_t)(
                        (ks * 16 + b3 * 8 + l7) * 136 + nb + b4 * 8);
                    ldsm4t(bfr[j2], addr);
                }
            }
            #pragma unroll
            for (int j2 = 0; j2 < 4; j2++) {
                mma16(acc[0][2*j2],     af[0], bfr[j2][0], bfr[j2][1]);
                mma16(acc[1][2*j2],     af[1], bfr[j2][0], bfr[j2][1]);
                mma16(acc[0][2*j2 + 1], af[0], bfr[j2][2], bfr[j2][3]);
                mma16(acc[1][2*j2 + 1], af[1], bfr[j2][2], bfr[j2][3]);
            }
        }
        __syncthreads();
    }

    // -------- epilogue --------
    if (OUTF == 0) {
        bf16* C = (bf16*)Cv + (size_t)bz * sC;
        #pragma unroll
        for (int i = 0; i < 2; i++) {
            int m = M0 + wm * 32 + i * 16 + g;
            float bm0 = bias ? bias[m]     : 0.f;
            float bm1 = bias ? bias[m + 8] : 0.f;
            #pragma unroll
            for (int j = 0; j < 8; j++) {
                int n = N0 + wn * 64 + j * 8 + 2 * t;
                __nv_bfloat162 v0 = __floats2bfloat162_rn(
                    acc[i][j][0] * alpha + bm0, acc[i][j][1] * alpha + bm0);
                __nv_bfloat162 v1 = __floats2bfloat162_rn(
                    acc[i][j][2] * alpha + bm1, acc[i][j][3] * alpha + bm1);
                *(__nv_bfloat162*)(C + (size_t)m * ldc + n)       = v0;
                *(__nv_bfloat162*)(C + (size_t)(m + 8) * ldc + n) = v1;
            }
        }
    } else {
        float* C = (float*)Cv + (size_t)bz * sC;
        const float* R = resid + (size_t)bz * sR;
        #pragma unroll
        for (int i = 0; i < 2; i++) {
            int m = M0 + wm * 32 + i * 16 + g;
            float bm0 = bias ? bias[m]     : 0.f;
            float bm1 = bias ? bias[m + 8] : 0.f;
            #pragma unroll
            for (int j = 0; j < 8; j++) {
                int n = N0 + wn * 64 + j * 8 + 2 * t;
                float2 r0 = *(const float2*)(R + (size_t)m * ldc + n);
                float2 r1 = *(const float2*)(R + (size_t)(m + 8) * ldc + n);
                float2 v0, v1;
                v0.x = acc[i][j][0] * alpha + bm0 + r0.x;
                v0.y = acc[i][j][1] * alpha + bm0 + r0.y;
                v1.x = acc[i][j][2] * alpha + bm1 + r1.x;
                v1.y = acc[i][j][3] * alpha + bm1 + r1.y;
                *(float2*)(C + (size_t)m * ldc + n)       = v0;
                *(float2*)(C + (size_t)(m + 8) * ldc + n) = v1;
            }
        }
    }
}

// ---------------------------------------------------------------------------
extern "C" void kernel_launch(void* const* d_in, const int* in_sizes, int n_in,
                              void* d_out, int out_size) {
    const float* x    = (const float*)d_in[0];
    const float* gn_w = (const float*)d_in[1];
    const float* gn_b = (const float*)d_in[2];
    const float* wq   = (const float*)d_in[3];
    const float* bq   = (const float*)d_in[4];
    const float* wk   = (const float*)d_in[5];
    const float* bk   = (const float*)d_in[6];
    const float* wv   = (const float*)d_in[7];
    const float* bv   = (const float*)d_in[8];
    const float* wo   = (const float*)d_in[9];
    const float* bo   = (const float*)d_in[10];
    float* out = (float*)d_out;

    void *p_xn, *p_q, *p_k, *p_v, *p_o, *p_attn, *p_w;
    cudaGetSymbolAddress(&p_xn,   g_xnb4);
    cudaGetSymbolAddress(&p_q,    g_qb4);
    cudaGetSymbolAddress(&p_k,    g_kb4);
    cudaGetSymbolAddress(&p_v,    g_vb4);
    cudaGetSymbolAddress(&p_o,    g_ob4);
    cudaGetSymbolAddress(&p_attn, g_attnb4);
    cudaGetSymbolAddress(&p_w,    g_wb4);

    bf16* xnb = (bf16*)p_xn;
    bf16* qb  = (bf16*)p_q;
    bf16* kb  = (bf16*)p_k;
    bf16* vb  = (bf16*)p_v;
    bf16* ob  = (bf16*)p_o;
    bf16* atb = (bf16*)p_attn;
    bf16* wqb = (bf16*)p_w;
    bf16* wkb = wqb + CCH * CCH;
    bf16* wvb = wkb + CCH * CCH;
    bf16* wob = wvb + CCH * CCH;

    const size_t SBb = (size_t)CCH * NTOK;    // bf16 feature stride
    const size_t SAb = (size_t)NTOK * NTOK;   // bf16 attn stride
    const size_t SBf = (size_t)CCH * NTOK;    // fp32 x/out stride
    const float scale = 0.0625f;              // 256^-0.5

    cudaFuncSetAttribute(bgemm<0,1,0>, cudaFuncAttributeMaxDynamicSharedMemorySize, SMEM_DYN);
    cudaFuncSetAttribute(bgemm<1,1,0>, cudaFuncAttributeMaxDynamicSharedMemorySize, SMEM_DYN);
    cudaFuncSetAttribute(bgemm<0,0,0>, cudaFuncAttributeMaxDynamicSharedMemorySize, SMEM_DYN);
    cudaFuncSetAttribute(bgemm<0,1,1>, cudaFuncAttributeMaxDynamicSharedMemorySize, SMEM_DYN);

    // 0) Weights fp32 -> bf16
    convw_kernel<<<256, 256>>>(wq, wk, wv, wo, wqb, wkb, wvb, wob);

    // 1) GroupNorm -> bf16
    groupnorm_kernel<<<BATCH * GROUPS, 256>>>(x, gn_w, gn_b, xnb);

    // 2) Q/K/V projections: A=W [m=o][k=c] (AST0), B=xn [k=c][n=i] (BST1)
    dim3 gproj(NTOK / 128, CCH / 128, BATCH);
    bgemm<0,1,0><<<gproj, 256, SMEM_DYN>>>(wqb, xnb, bq, nullptr, qb,
        CCH, CCH, NTOK, NTOK, 0, SBb, SBb, 0, 1.0f);
    bgemm<0,1,0><<<gproj, 256, SMEM_DYN>>>(wkb, xnb, bk, nullptr, kb,
        CCH, CCH, NTOK, NTOK, 0, SBb, SBb, 0, 1.0f);
    bgemm<0,1,0><<<gproj, 256, SMEM_DYN>>>(wvb, xnb, bv, nullptr, vb,
        CCH, CCH, NTOK, NTOK, 0, SBb, SBb, 0, 1.0f);

    // 3) Scores: A=q [k=c][m=i] (AST1), B=k [k=c][n=j] (BST1), alpha=scale
    dim3 gscore(NTOK / 128, NTOK / 128, BATCH);
    bgemm<1,1,0><<<gscore, 256, SMEM_DYN>>>(qb, kb, nullptr, nullptr, atb,
        CCH, NTOK, NTOK, NTOK, SBb, SBb, SAb, 0, scale);

    // 4) Row softmax (bf16 in/out, fp32 math)
    dim3 gsm(NTOK, BATCH);
    softmax_kernel<<<gsm, 256>>>(atb);

    // 5) PV: A=v [m=c][k=j] (AST0), B=P [n=i][k=j] (BST0)
    dim3 gpv(NTOK / 128, CCH / 128, BATCH);
    bgemm<0,0,0><<<gpv, 256, SMEM_DYN>>>(vb, atb, nullptr, nullptr, ob,
        NTOK, NTOK, NTOK, NTOK, SBb, SAb, SBb, 0, 1.0f);

    // 6) Output projection + bias + residual (fp32 out)
    bgemm<0,1,1><<<gproj, 256, SMEM_DYN>>>(wob, ob, bo, x, out,
        CCH, CCH, NTOK, NTOK, 0, SBb, SBf, SBf, 1.0f);
}

// round 5
// speedup vs baseline: 12.3587x; 1.1066x over previous
#include <cuda_runtime.h>
#include <cuda_bf16.h>
#include <cstdint>
#include <cstddef>

#define BATCH 4
#define CCH 256
#define NTOK 4096
#define GROUPS 32
#define CPG 8
#define EPSV 1e-6f

typedef __nv_bfloat16 bf16;

// ---------------- scratch (device globals) ----------------
__device__ uint4 g_xnb4 [(size_t)BATCH * CCH * NTOK / 8];          // GN out bf16
__device__ uint4 g_qkvb4[(size_t)3 * BATCH * CCH * NTOK / 8];      // packed q,k,v
__device__ uint4 g_ob4  [(size_t)BATCH * CCH * NTOK / 8];          // PV out
__device__ uint4 g_attnb4[(size_t)BATCH * NTOK * NTOK / 8];        // P (bf16)
__device__ uint4 g_wb4[4][CCH * CCH / 8];                          // bf16 weights
__device__ float g_biasqkv[3 * CCH];
__device__ float g_psum[(size_t)BATCH * NTOK * 32];                // partial row sums
__device__ float g_invs[BATCH * NTOK];                             // 1/rowsum

// ---------------- asm helpers ----------------
__device__ __forceinline__ uint32_t smem_u32(const void* p) {
    uint32_t a;
    asm("{ .reg .u64 t; cvta.to.shared.u64 t, %1; cvt.u32.u64 %0, t; }"
        : "=r"(a) : "l"(p));
    return a;
}
__device__ __forceinline__ void ldsm4(uint32_t* r, uint32_t a) {
    asm volatile("ldmatrix.sync.aligned.m8n8.x4.shared.b16 {%0,%1,%2,%3}, [%4];"
        : "=r"(r[0]), "=r"(r[1]), "=r"(r[2]), "=r"(r[3]) : "r"(a));
}
__device__ __forceinline__ void ldsm4t(uint32_t* r, uint32_t a) {
    asm volatile("ldmatrix.sync.aligned.m8n8.x4.trans.shared.b16 {%0,%1,%2,%3}, [%4];"
        : "=r"(r[0]), "=r"(r[1]), "=r"(r[2]), "=r"(r[3]) : "r"(a));
}
__device__ __forceinline__ void mma16(float* c, const uint32_t* a,
                                      uint32_t b0, uint32_t b1) {
    asm volatile(
        "mma.sync.aligned.m16n8k16.row.col.f32.bf16.bf16.f32 "
        "{%0,%1,%2,%3}, {%4,%5,%6,%7}, {%8,%9}, {%0,%1,%2,%3};"
        : "+f"(c[0]), "+f"(c[1]), "+f"(c[2]), "+f"(c[3])
        : "r"(a[0]), "r"(a[1]), "r"(a[2]), "r"(a[3]), "r"(b0), "r"(b1));
}
__device__ __forceinline__ void cp16(uint32_t d, const void* s) {
    asm volatile("cp.async.cg.shared.global [%0], [%1], 16;" :: "r"(d), "l"(s));
}

// ---------------------------------------------------------------------------
// Weights fp32 -> bf16 (packed) + bias packing
// ---------------------------------------------------------------------------
__global__ void convw_kernel(const float* wq, const float* wk,
                             const float* wv, const float* wo,
                             const float* bq, const float* bk, const float* bv,
                             bf16* w0, bf16* w1, bf16* w2, bf16* w3,
                             float* biasqkv) {
    int i = blockIdx.x * 256 + threadIdx.x;
    w0[i] = __float2bfloat16(wq[i]);
    w1[i] = __float2bfloat16(wk[i]);
    w2[i] = __float2bfloat16(wv[i]);
    w3[i] = __float2bfloat16(wo[i]);
    if (i < CCH) {
        biasqkv[i]           = bq[i];
        biasqkv[CCH + i]     = bk[i];
        biasqkv[2 * CCH + i] = bv[i];
    }
}

// ---------------------------------------------------------------------------
// GroupNorm: fp32 in, bf16 out
// ---------------------------------------------------------------------------
__global__ void groupnorm_kernel(const float* __restrict__ x,
                                 const float* __restrict__ w,
                                 const float* __restrict__ b,
                                 bf16* __restrict__ xnb) {
    int g  = blockIdx.x % GROUPS;
    int bb = blockIdx.x / GROUPS;
    const float4* xp = (const float4*)(x + ((size_t)bb * CCH + g * CPG) * NTOK);
    bf16* op = xnb + ((size_t)bb * CCH + g * CPG) * NTOK;
    int tid = threadIdx.x;
    const int n4 = CPG * NTOK / 4;

    float s = 0.f, s2 = 0.f;
    for (int i = tid; i < n4; i += 256) {
        float4 v = xp[i];
        s  += v.x + v.y + v.z + v.w;
        s2 += v.x*v.x + v.y*v.y + v.z*v.z + v.w*v.w;
    }
    __shared__ float sh0[256], sh1[256];
    sh0[tid] = s; sh1[tid] = s2;
    __syncthreads();
    for (int off = 128; off > 0; off >>= 1) {
        if (tid < off) { sh0[tid] += sh0[tid + off]; sh1[tid] += sh1[tid + off]; }
        __syncthreads();
    }
    const float nall = (float)(CPG * NTOK);
    float mean = sh0[0] / nall;
    float var  = sh1[0] / nall - mean * mean;
    float rstd = rsqrtf(var + EPSV);

    for (int i = tid; i < n4; i += 256) {
        int ch = g * CPG + (i * 4) / NTOK;
        float sc = rstd * w[ch];
        float sb = b[ch] - mean * sc;
        float4 v = xp[i];
        __nv_bfloat162 h0 = __floats2bfloat162_rn(v.x * sc + sb, v.y * sc + sb);
        __nv_bfloat162 h1 = __floats2bfloat162_rn(v.z * sc + sb, v.w * sc + sb);
        uint2 u;
        u.x = *(uint32_t*)&h0; u.y = *(uint32_t*)&h1;
        *(uint2*)(op + i * 4) = u;
    }
}

// ---------------------------------------------------------------------------
// Row-sum reduce + invert: 16384 rows x 32 partials
// ---------------------------------------------------------------------------
__global__ void rowinv_kernel(const float* __restrict__ psum,
                              float* __restrict__ invs) {
    int i = blockIdx.x * 256 + threadIdx.x;
    const float* p = psum + (size_t)i * 32;
    float s = 0.f;
    #pragma unroll
    for (int j = 0; j < 32; j++) s += p[j];
    invs[i] = 1.f / s;
}

// ---------------------------------------------------------------------------
// bf16 GEMM, tile 128x128, BK=64, 256 threads (8 warps, warp tile 32x64),
// 3-stage cp.async ring (one __syncthreads per k-tile), ldmatrix + m16n8k16.
// AST/BST: operand layouts as R4.
// OUTF 0: bf16 out (+bias)       OUTF 1: fp32 out + bias + resid
// OUTF 2: p=exp(acc*alpha) bf16 out + partial row sums to psum
// OUTF 3: bf16 out scaled by invs[n]
// QKV 1: blockIdx.y selects matrix (y>>1) and row half (y&1)
// ---------------------------------------------------------------------------
#define ABYTES 18432u
#define BUFBYTES 36864u
#define SMEM_DYN (3 * 36864)

template <int AST, int BST, int OUTF, int QKV>
__global__ void __launch_bounds__(256, 2)
bgemm(const bf16* __restrict__ A, const bf16* __restrict__ B,
      const float* __restrict__ bias, const float* __restrict__ resid,
      void* __restrict__ Cv, float* __restrict__ psum,
      const float* __restrict__ invs,
      int K, int lda, int ldb, int ldc,
      size_t sA, size_t sB, size_t sC, size_t sR, float alpha) {
    extern __shared__ __align__(16) char smem[];
    const int bz = blockIdx.z;

    int M0;
    size_t cext = 0;
    if (QKV) {
        int mat = blockIdx.y >> 1;
        A    += (size_t)mat * (CCH * CCH);
        bias += mat * CCH;
        cext  = (size_t)mat * BATCH * (size_t)CCH * NTOK;
        M0 = (blockIdx.y & 1) * 128;
    } else {
        M0 = blockIdx.y * 128;
    }
    A += (size_t)bz * sA;
    B += (size_t)bz * sB;

    const int N0 = blockIdx.x * 128;
    const int tid  = threadIdx.x;
    const int lane = tid & 31;
    const int wid  = tid >> 5;
    const int wm = wid >> 1;
    const int wn = wid & 1;
    const int g  = lane >> 2;
    const int t  = lane & 3;
    const int l7  = lane & 7;
    const int l15 = lane & 15;
    const int b3 = (lane >> 3) & 1;
    const int b4 = (lane >> 4) & 1;

    const uint32_t smem_u = smem_u32(smem);

    float acc[2][8][4];
    #pragma unroll
    for (int i = 0; i < 2; i++)
        #pragma unroll
        for (int j = 0; j < 8; j++)
            #pragma unroll
            for (int q = 0; q < 4; q++) acc[i][j][q] = 0.f;

    const int KT = K >> 6;

    auto stage = [&](int kt, int buf) {
        uint32_t ab = smem_u + (uint32_t)buf * BUFBYTES;
        uint32_t bbs = ab + ABYTES;
        int k0 = kt << 6;
        #pragma unroll
        for (int i = 0; i < 4; i++) {
            int c = tid + i * 256;
            if (AST == 0) {
                int m = c >> 3, kc = c & 7;
                cp16(ab + (uint32_t)(m * 72 + kc * 8) * 2,
                     A + (size_t)(M0 + m) * lda + k0 + kc * 8);
            } else {
                int k = c >> 4, mc = c & 15;
                cp16(ab + (uint32_t)(k * 136 + mc * 8) * 2,
                     A + (size_t)(k0 + k) * lda + M0 + mc * 8);
            }
        }
        #pragma unroll
        for (int i = 0; i < 4; i++) {
            int c = tid + i * 256;
            if (BST == 0) {
                int n = c >> 3, kc = c & 7;
                cp16(bbs + (uint32_t)(n * 72 + kc * 8) * 2,
                     B + (size_t)(N0 + n) * ldb + k0 + kc * 8);
            } else {
                int k = c >> 4, nc = c & 15;
                cp16(bbs + (uint32_t)(k * 136 + nc * 8) * 2,
                     B + (size_t)(k0 + k) * ldb + N0 + nc * 8);
            }
        }
    };

    stage(0, 0);
    asm volatile("cp.async.commit_group;" ::: "memory");
    stage(1, 1);
    asm volatile("cp.async.commit_group;" ::: "memory");

    for (int kt = 0; kt < KT; kt++) {
        asm volatile("cp.async.wait_group 1;" ::: "memory");
        __syncthreads();

        // prefetch kt+2 into the ring slot freed by kt-1
        if (kt + 2 < KT) stage(kt + 2, (kt + 2) % 3);
        asm volatile("cp.async.commit_group;" ::: "memory");

        uint32_t ab = smem_u + (uint32_t)(kt % 3) * BUFBYTES;
        uint32_t bbs = ab + ABYTES;

        #pragma unroll
        for (int ks = 0; ks < 4; ks++) {
            uint32_t af[2][4];
            #pragma unroll
            for (int i = 0; i < 2; i++) {
                if (AST == 0) {
                    uint32_t addr = ab + 2u * (uint32_t)(
                        (wm * 32 + i * 16 + l15) * 72 + ks * 16 + b4 * 8);
                    ldsm4(af[i], addr);
                } else {
                    uint32_t addr = ab + 2u * (uint32_t)(
                        (ks * 16 + b4 * 8 + l7) * 136 + wm * 32 + i * 16 + b3 * 8);
                    ldsm4t(af[i], addr);
                }
            }
            uint32_t bfr[4][4];
            #pragma unroll
            for (int j2 = 0; j2 < 4; j2++) {
                int nb = wn * 64 + j2 * 16;
                if (BST == 0) {
                    uint32_t addr = bbs + 2u * (uint32_t)(
                        (nb + b4 * 8 + l7) * 72 + ks * 16 + b3 * 8);
                    ldsm4(bfr[j2], addr);
                } else {
                    uint32_t addr = bbs + 2u * (uint32_t)(
                        (ks * 16 + b3 * 8 + l7) * 136 + nb + b4 * 8);
                    ldsm4t(bfr[j2], addr);
                }
            }
            #pragma unroll
            for (int j2 = 0; j2 < 4; j2++) {
                mma16(acc[0][2*j2],     af[0], bfr[j2][0], bfr[j2][1]);
                mma16(acc[1][2*j2],     af[1], bfr[j2][0], bfr[j2][1]);
                mma16(acc[0][2*j2 + 1], af[0], bfr[j2][2], bfr[j2][3]);
                mma16(acc[1][2*j2 + 1], af[1], bfr[j2][2], bfr[j2][3]);
            }
        }
    }

    // -------- epilogues --------
    if (OUTF == 0) {
        bf16* C = (bf16*)Cv + cext + (size_t)bz * sC;
        #pragma unroll
        for (int i = 0; i < 2; i++) {
            int m = M0 + wm * 32 + i * 16 + g;
            float bm0 = bias ? bias[m]     : 0.f;
            float bm1 = bias ? bias[m + 8] : 0.f;
            #pragma unroll
            for (int j = 0; j < 8; j++) {
                int n = N0 + wn * 64 + j * 8 + 2 * t;
                __nv_bfloat162 v0 = __floats2bfloat162_rn(
                    acc[i][j][0] * alpha + bm0, acc[i][j][1] * alpha + bm0);
                __nv_bfloat162 v1 = __floats2bfloat162_rn(
                    acc[i][j][2] * alpha + bm1, acc[i][j][3] * alpha + bm1);
                *(__nv_bfloat162*)(C + (size_t)m * ldc + n)       = v0;
                *(__nv_bfloat162*)(C + (size_t)(m + 8) * ldc + n) = v1;
            }
        }
    } else if (OUTF == 1) {
        float* C = (float*)Cv + (size_t)bz * sC;
        const float* R = resid + (size_t)bz * sR;
        #pragma unroll
        for (int i = 0; i < 2; i++) {
            int m = M0 + wm * 32 + i * 16 + g;
            float bm0 = bias[m];
            float bm1 = bias[m + 8];
            #pragma unroll
            for (int j = 0; j < 8; j++) {
                int n = N0 + wn * 64 + j * 8 + 2 * t;
                float2 r0 = *(const float2*)(R + (size_t)m * ldc + n);
                float2 r1 = *(const float2*)(R + (size_t)(m + 8) * ldc + n);
                float2 v0, v1;
                v0.x = acc[i][j][0] + bm0 + r0.x;
                v0.y = acc[i][j][1] + bm0 + r0.y;
                v1.x = acc[i][j][2] + bm1 + r1.x;
                v1.y = acc[i][j][3] + bm1 + r1.y;
                *(float2*)(C + (size_t)m * ldc + n)       = v0;
                *(float2*)(C + (size_t)(m + 8) * ldc + n) = v1;
            }
        }
    } else if (OUTF == 2) {
        // exp epilogue + deterministic partial row sums
        bf16* C = (bf16*)Cv + (size_t)bz * sC;
        float* ps = (float*)smem;          // [2][128], aliases tile smem
        __syncthreads();                   // all compute done before reuse
        #pragma unroll
        for (int i = 0; i < 2; i++) {
            int m = M0 + wm * 32 + i * 16 + g;
            float sr0 = 0.f, sr1 = 0.f;
            #pragma unroll
            for (int j = 0; j < 8; j++) {
                int n = N0 + wn * 64 + j * 8 + 2 * t;
                float e0 = __expf(acc[i][j][0] * alpha);
                float e1 = __expf(acc[i][j][1] * alpha);
                float e2 = __expf(acc[i][j][2] * alpha);
                float e3 = __expf(acc[i][j][3] * alpha);
                sr0 += e0 + e1;
                sr1 += e2 + e3;
                *(__nv_bfloat162*)(C + (size_t)m * ldc + n) =
                    __floats2bfloat162_rn(e0, e1);
                *(__nv_bfloat162*)(C + (size_t)(m + 8) * ldc + n) =
                    __floats2bfloat162_rn(e2, e3);
            }
            sr0 += __shfl_xor_sync(0xffffffffu, sr0, 1);
            sr0 += __shfl_xor_sync(0xffffffffu, sr0, 2);
            sr1 += __shfl_xor_sync(0xffffffffu, sr1, 1);
            sr1 += __shfl_xor_sync(0xffffffffu, sr1, 2);
            if (t == 0) {
                int r = wm * 32 + i * 16 + g;
                ps[wn * 128 + r]     = sr0;
                ps[wn * 128 + r + 8] = sr1;
            }
        }
        __syncthreads();
        if (tid < 128) {
            float tot = ps[tid] + ps[128 + tid];
            psum[((size_t)bz * NTOK + M0 + tid) * 32 + blockIdx.x] = tot;
        }
    } else {
        // OUTF == 3: normalize by invs[n]
        bf16* C = (bf16*)Cv + (size_t)bz * sC;
        const float* iv = invs + (size_t)bz * NTOK;
        #pragma unroll
        for (int i = 0; i < 2; i++) {
            int m = M0 + wm * 32 + i * 16 + g;
            #pragma unroll
            for (int j = 0; j < 8; j++) {
                int n = N0 + wn * 64 + j * 8 + 2 * t;
                float2 w2 = *(const float2*)(iv + n);
                __nv_bfloat162 v0 = __floats2bfloat162_rn(
                    acc[i][j][0] * w2.x, acc[i][j][1] * w2.y);
                __nv_bfloat162 v1 = __floats2bfloat162_rn(
                    acc[i][j][2] * w2.x, acc[i][j][3] * w2.y);
                *(__nv_bfloat162*)(C + (size_t)m * ldc + n)       = v0;
                *(__nv_bfloat162*)(C + (size_t)(m + 8) * ldc + n) = v1;
            }
        }
    }
}

// ---------------------------------------------------------------------------
extern "C" void kernel_launch(void* const* d_in, const int* in_sizes, int n_in,
                              void* d_out, int out_size) {
    const float* x    = (const float*)d_in[0];
    const float* gn_w = (const float*)d_in[1];
    const float* gn_b = (const float*)d_in[2];
    const float* wq   = (const float*)d_in[3];
    const float* bq   = (const float*)d_in[4];
    const float* wk   = (const float*)d_in[5];
    const float* bk   = (const float*)d_in[6];
    const float* wv   = (const float*)d_in[7];
    const float* bv   = (const float*)d_in[8];
    const float* wo   = (const float*)d_in[9];
    const float* bo   = (const float*)d_in[10];
    float* out = (float*)d_out;

    void *p_xn, *p_qkv, *p_o, *p_attn, *p_w, *p_bias, *p_psum, *p_inv;
    cudaGetSymbolAddress(&p_xn,   g_xnb4);
    cudaGetSymbolAddress(&p_qkv,  g_qkvb4);
    cudaGetSymbolAddress(&p_o,    g_ob4);
    cudaGetSymbolAddress(&p_attn, g_attnb4);
    cudaGetSymbolAddress(&p_w,    g_wb4);
    cudaGetSymbolAddress(&p_bias, g_biasqkv);
    cudaGetSymbolAddress(&p_psum, g_psum);
    cudaGetSymbolAddress(&p_inv,  g_invs);

    bf16* xnb  = (bf16*)p_xn;
    bf16* qkvb = (bf16*)p_qkv;
    bf16* atb  = (bf16*)p_attn;
    bf16* ob   = (bf16*)p_o;
    bf16* wqb  = (bf16*)p_w;
    bf16* wob  = wqb + 3 * CCH * CCH;
    float* biasqkv = (float*)p_bias;
    float* psum = (float*)p_psum;
    float* invs = (float*)p_inv;

    const size_t SBb = (size_t)CCH * NTOK;
    const size_t SAb = (size_t)NTOK * NTOK;
    bf16* qb = qkvb;
    bf16* kb = qkvb + BATCH * SBb;
    bf16* vb = qkvb + 2 * BATCH * SBb;
    const float scale = 0.0625f;

    cudaFuncSetAttribute(bgemm<0,1,0,1>, cudaFuncAttributeMaxDynamicSharedMemorySize, SMEM_DYN);
    cudaFuncSetAttribute(bgemm<1,1,2,0>, cudaFuncAttributeMaxDynamicSharedMemorySize, SMEM_DYN);
    cudaFuncSetAttribute(bgemm<0,0,3,0>, cudaFuncAttributeMaxDynamicSharedMemorySize, SMEM_DYN);
    cudaFuncSetAttribute(bgemm<0,1,1,0>, cudaFuncAttributeMaxDynamicSharedMemorySize, SMEM_DYN);

    // 0) convert+pack weights / biases
    convw_kernel<<<256, 256>>>(wq, wk, wv, wo, bq, bk, bv,
                               wqb, wqb + CCH*CCH, wqb + 2*CCH*CCH, wob, biasqkv);

    // 1) GroupNorm -> bf16
    groupnorm_kernel<<<BATCH * GROUPS, 256>>>(x, gn_w, gn_b, xnb);

    // 2) fused QKV projection (grid.y = 3 matrices x 2 row-halves)
    bgemm<0,1,0,1><<<dim3(NTOK/128, 6, BATCH), 256, SMEM_DYN>>>(
        wqb, xnb, biasqkv, nullptr, qkvb, nullptr, nullptr,
        CCH, CCH, NTOK, NTOK, 0, SBb, SBb, 0, 1.0f);

    // 3) scores + exp + partial row sums
    bgemm<1,1,2,0><<<dim3(NTOK/128, NTOK/128, BATCH), 256, SMEM_DYN>>>(
        qb, kb, nullptr, nullptr, atb, psum, nullptr,
        CCH, NTOK, NTOK, NTOK, SBb, SBb, SAb, 0, scale);

    // 4) reduce + invert row sums
    rowinv_kernel<<<BATCH * NTOK / 256, 256>>>(psum, invs);

    // 5) PV with normalization epilogue
    bgemm<0,0,3,0><<<dim3(NTOK/128, CCH/128, BATCH), 256, SMEM_DYN>>>(
        vb, atb, nullptr, nullptr, ob, nullptr, invs,
        NTOK, NTOK, NTOK, NTOK, SBb, SAb, SBb, 0, 1.0f);

    // 6) output projection + bias + residual (fp32 out)
    bgemm<0,1,1,0><<<dim3(NTOK/128, CCH/128, BATCH), 256, SMEM_DYN>>>(
        wob, ob, bo, x, out, nullptr, nullptr,
        CCH, CCH, NTOK, NTOK, 0, SBb, SBb, SBb, 1.0f);
}